// round 16
// baseline (speedup 1.0000x reference)
#include <cuda_runtime.h>
#include <cstdint>

#define B_  8
#define N_  256
#define DN  64
#define DE  32
#define DC  64
#define DO_ 60
#define CPB  37           // CTAs per batch
#define GRID (8*CPB)      // 296

__device__ __align__(16) float g_pr  [B_*N_*DC];
__device__ __align__(16) float g_psb [B_*N_*DC];
__device__ __align__(16) float g_part[B_*N_*8*DC];   // per-warp partial aggs (4 MB)

// ---------------------------------------------------------------------------
// Kernel A: per-node precompute. 8 nodes/block, 2 nodes/thread -> 6 parallel
// FMA chains, W loads amortized over 2 nodes, node rows smem-broadcast.
// ---------------------------------------------------------------------------
#define PCN 8
__global__ void __launch_bounds__(256) precompute_kernel(
    const float* __restrict__ node,
    const float* __restrict__ W_e,
    const float* __restrict__ b_e,
    const float* __restrict__ W_n,
    const float* __restrict__ b_n,
    float* __restrict__ out) {

    __shared__ float nrow[PCN][DN];        // 2 KB
    const int tid = threadIdx.x;
    const int c   = tid & 63;
    const int ng  = tid >> 6;              // 0..3
    const int bn0 = blockIdx.x * PCN;

    for (int i = tid; i < PCN*DN; i += 256)
        nrow[i >> 6][i & 63] = node[bn0*DN + i];
    __syncthreads();

    const int n0 = 2*ng, n1 = 2*ng + 1;
    float aR0 = 0.f, aR1 = 0.f, aS0 = 0.f, aS1 = 0.f, aO0 = 0.f, aO1 = 0.f;

    #pragma unroll 16
    for (int k = 0; k < DN; k++) {
        const float wR = W_e[(DE      + k)*DC + c];
        const float wS = W_e[(DE + DN + k)*DC + c];
        const float wO = W_n[k*DO_ + c];           // in-bounds; unused for c>=60
        const float nv0 = nrow[n0][k];
        const float nv1 = nrow[n1][k];
        aR0 = fmaf(nv0, wR, aR0);  aR1 = fmaf(nv1, wR, aR1);
        aS0 = fmaf(nv0, wS, aS0);  aS1 = fmaf(nv1, wS, aS1);
        aO0 = fmaf(nv0, wO, aO0);  aO1 = fmaf(nv1, wO, aO1);
    }

    g_pr [(bn0 + n0)*DC + c] = aR0;
    g_pr [(bn0 + n1)*DC + c] = aR1;
    const float be = b_e[c];
    g_psb[(bn0 + n0)*DC + c] = aS0 + be;
    g_psb[(bn0 + n1)*DC + c] = aS1 + be;
    if (c < DO_) {
        const float bo = b_n[c];
        out[(size_t)(bn0 + n0)*DO_ + c] = aO0 + bo;
        out[(size_t)(bn0 + n1)*DO_ + c] = aO1 + bo;
    }
}

// ---------------------------------------------------------------------------
// tf32 / math / async helpers
// ---------------------------------------------------------------------------
__device__ __forceinline__ uint32_t tf32r(float f) {
    uint32_t u;
    asm("cvt.rna.tf32.f32 %0, %1;" : "=r"(u) : "f"(f));
    return u;
}
__device__ __forceinline__ void mma_1688(float c[4],
                                         const uint32_t a[4],
                                         uint32_t b0, uint32_t b1) {
    asm volatile("mma.sync.aligned.m16n8k8.row.col.f32.tf32.tf32.f32 "
                 "{%0,%1,%2,%3}, {%4,%5,%6,%7}, {%8,%9}, {%0,%1,%2,%3};"
                 : "+f"(c[0]), "+f"(c[1]), "+f"(c[2]), "+f"(c[3])
                 : "r"(a[0]), "r"(a[1]), "r"(a[2]), "r"(a[3]), "r"(b0), "r"(b1));
}
__device__ __forceinline__ void cp16(uint32_t smem_addr, const void* gptr) {
    asm volatile("cp.async.cg.shared.global [%0], [%1], 16;"
                 :: "r"(smem_addr), "l"(gptr));
}
// leaky-relu then scaled accumulate: u += a * max(x, 0.01x)
__device__ __forceinline__ float lracc(float u, float a, float x) {
    return fmaf(a, fmaxf(x, 0.01f * x), u);
}

#define ESTRIDE 36    // bank = 4g + t  -> conflict-free A-frag loads
#define PSTRIDE 268   // float2 stride; conflict-free per 16-lane phase

// Dynamic smem layout (bytes)
#define OFF_E0   0u          // half-tile buf0: 128*36*4 = 18432
#define OFF_E1   18432u      // half-tile buf1: 18432
#define OFF_PSB  36864u      // psb2 float2[32][268] = 68608
#define OFF_PRS  105472u     // pr staged: 7*64 f32 = 1792
#define SMEM_DYN 107264u     // -> 2 CTAs/SM

// ---------------------------------------------------------------------------
// Kernel B: batch-locked persistent CTAs; psb packed float2 in smem; B-frags
// register-resident; warp-private cp.async E pipeline. NO CTA barrier in the
// receiver loop: per-warp partials go to gmem; fold kernel combines.
// ---------------------------------------------------------------------------
__global__ void __launch_bounds__(256, 2) edge_kernel(
    const float* __restrict__ edge_attr,
    const float* __restrict__ adj,
    const float* __restrict__ W_e) {

    extern __shared__ __align__(16) unsigned char dynsm[];
    float2* psb2 = (float2*)(dynsm + OFF_PSB);
    float*  prS  = (float*) (dynsm + OFF_PRS);
    const uint32_t esm0 = (uint32_t)__cvta_generic_to_shared(dynsm);

    const int tid  = threadIdx.x;
    const int bx   = blockIdx.x;
    const int wid  = tid >> 5;             // 0..7
    const int lane = tid & 31;
    const int g    = lane >> 2;            // 0..7
    const int t    = lane & 3;             // 0..3

    const int batch = bx / CPB;
    const int cb    = bx % CPB;
    const int rs    = (cb * N_) / CPB;
    const int re    = ((cb + 1) * N_) / CPB;
    const int nr    = re - rs;             // 6 or 7
    const int bn0   = batch * N_ + rs;

    // warp-private E row mapping: lane l loads rows 16w + (l>>3) + 4i, chunk l&7
    const int erow = 16*wid + (lane >> 3);
    const int eq   = lane & 7;

    // --- fire first half-load (receiver bn0, half 0) into buf0 ---
    {
        const float* esrc = edge_attr + (size_t)bn0 * (N_*DE);
        #pragma unroll
        for (int i = 0; i < 4; i++) {
            int r = erow + 4*i;
            cp16(esm0 + (uint32_t)(r*ESTRIDE + eq*4)*4u, esrc + r*DE + eq*4);
        }
        asm volatile("cp.async.commit_group;");
    }

    // --- B-fragments register-resident (one-time gmem loads, L2-shared) ---
    uint32_t bfr[8][4][2];
    #pragma unroll
    for (int nt = 0; nt < 8; nt++)
        #pragma unroll
        for (int ks = 0; ks < 4; ks++) {
            bfr[nt][ks][0] = tf32r(__ldg(W_e + (8*ks + t    )*DC + 8*nt + g));
            bfr[nt][ks][1] = tf32r(__ldg(W_e + (8*ks + t + 4)*DC + 8*nt + g));
        }

    // --- stage psb2 for this batch (once): cp = lane, s = 8i + wid ---
    {
        const float2* psrc = (const float2*)g_psb + (size_t)batch * (N_*DC/2);
        #pragma unroll
        for (int i = 0; i < 32; i++) {
            const int s  = 8*i + wid;      // 0..255
            const int cp = lane;           // 0..31
            psb2[cp*PSTRIDE + s] = psrc[s*32 + cp];
        }
    }
    // --- stage pr for all this CTA's receivers (once) ---
    for (int idx = tid; idx < nr*DC; idx += 256)
        prS[idx] = g_pr[(size_t)bn0*DC + idx];
    __syncthreads();                        // the ONLY CTA barrier

    for (int ri = 0; ri < nr; ri++) {
        const int bn = bn0 + ri;
        const float* prp = prS + ri*DC + 2*t;   // smem

        float ux[8], uy[8];
        #pragma unroll
        for (int nt = 0; nt < 8; nt++) { ux[nt] = 0.f; uy[nt] = 0.f; }

        #pragma unroll
        for (int h = 0; h < 2; h++) {
            const int m = 2*ri + h;

            // --- prefetch next half (warp-private rows) ---
            if (m + 1 < 2*nr) {
                const int rn = (m + 1) >> 1, hn = (m + 1) & 1;
                const float* esrc = edge_attr
                    + (size_t)(bn0 + rn) * (N_*DE) + hn * (128*DE);
                const uint32_t eb = esm0 + (uint32_t)((m + 1) & 1) * OFF_E1;
                #pragma unroll
                for (int i = 0; i < 4; i++) {
                    int r = erow + 4*i;
                    cp16(eb + (uint32_t)(r*ESTRIDE + eq*4)*4u, esrc + r*DE + eq*4);
                }
                asm volatile("cp.async.commit_group;");
                asm volatile("cp.async.wait_group 1;" ::: "memory");
            } else {
                asm volatile("cp.async.wait_group 0;" ::: "memory");
            }
            __syncwarp();                   // intra-warp visibility only

            const int sg_lo = h*128 + 16*wid + g;    // global sender of row lo
            const float a_lo = __ldg(adj + (size_t)bn*N_ + sg_lo);
            const float a_hi = __ldg(adj + (size_t)bn*N_ + sg_lo + 8);

            // --- A fragments from current half buffer (own rows only) ---
            const uint32_t* Eb = (const uint32_t*)(dynsm + (m & 1)*OFF_E1);
            const int lo = 16*wid + g, hi = lo + 8;
            uint32_t afr[4][4];
            #pragma unroll
            for (int ks = 0; ks < 4; ks++) {
                const int k0 = 8*ks + t;
                afr[ks][0] = tf32r(__uint_as_float(Eb[lo*ESTRIDE + k0    ]));
                afr[ks][1] = tf32r(__uint_as_float(Eb[hi*ESTRIDE + k0    ]));
                afr[ks][2] = tf32r(__uint_as_float(Eb[lo*ESTRIDE + k0 + 4]));
                afr[ks][3] = tf32r(__uint_as_float(Eb[hi*ESTRIDE + k0 + 4]));
            }

            #pragma unroll
            for (int nt = 0; nt < 8; nt += 2) {
                const int cpA = 4*nt + t;          // channel pair 8nt+2t
                const int cpB = cpA + 4;           // channel pair 8(nt+1)+2t
                const float2 prA = *(const float2*)(prp + 8*nt);
                const float2 prB = *(const float2*)(prp + 8*nt + 8);

                const float2 pAlo = psb2[cpA*PSTRIDE + sg_lo];
                const float2 pAhi = psb2[cpA*PSTRIDE + sg_lo + 8];
                const float2 pBlo = psb2[cpB*PSTRIDE + sg_lo];
                const float2 pBhi = psb2[cpB*PSTRIDE + sg_lo + 8];

                float acc0[4] = { pAlo.x + prA.x, pAlo.y + prA.y,
                                  pAhi.x + prA.x, pAhi.y + prA.y };
                float acc1[4] = { pBlo.x + prB.x, pBlo.y + prB.y,
                                  pBhi.x + prB.x, pBhi.y + prB.y };

                #pragma unroll
                for (int ks = 0; ks < 4; ks++) {
                    mma_1688(acc0, afr[ks], bfr[nt    ][ks][0], bfr[nt    ][ks][1]);
                    mma_1688(acc1, afr[ks], bfr[nt + 1][ks][0], bfr[nt + 1][ks][1]);
                }

                ux[nt]   = lracc(lracc(ux[nt],   a_lo, acc0[0]), a_hi, acc0[2]);
                uy[nt]   = lracc(lracc(uy[nt],   a_lo, acc0[1]), a_hi, acc0[3]);
                ux[nt+1] = lracc(lracc(ux[nt+1], a_lo, acc1[0]), a_hi, acc1[2]);
                uy[nt+1] = lracc(lracc(uy[nt+1], a_lo, acc1[1]), a_hi, acc1[3]);
            }
        } // halves

        // --- cross-lane butterfly over the 8 groups; lanes 0-3 own channels ---
        #pragma unroll
        for (int nt = 0; nt < 8; nt++) {
            #pragma unroll
            for (int st = 4; st <= 16; st <<= 1) {
                ux[nt] += __shfl_xor_sync(0xffffffffu, ux[nt], st);
                uy[nt] += __shfl_xor_sync(0xffffffffu, uy[nt], st);
            }
        }
        // --- warp-private partials straight to gmem: no CTA sync needed ---
        if (lane < 4) {
            float* pp = g_part + ((size_t)bn*8 + wid)*DC;
            #pragma unroll
            for (int nt = 0; nt < 8; nt++)
                *(float2*)(pp + 8*nt + 2*t) = make_float2(ux[nt], uy[nt]);
        }
    } // receivers
}

// ---------------------------------------------------------------------------
// Kernel C: fold. agg[c] = sum_w part[bn][w][c]; out[bn] += agg @ W_n[64:128].
// ---------------------------------------------------------------------------
__global__ void __launch_bounds__(256) fold_kernel(const float* __restrict__ W_n,
                                                   float* __restrict__ out) {
    __shared__ float agg[4][DC];
    const int tid = threadIdx.x;
    const int r4  = tid >> 6;               // 0..3
    const int o   = tid & 63;               // 0..63
    const int bn  = blockIdx.x*4 + r4;

    const float* pp = g_part + (size_t)bn*8*DC + o;
    float a = 0.f;
    #pragma unroll
    for (int w = 0; w < 8; w++) a += pp[w*DC];
    agg[r4][o] = a;
    __syncthreads();

    if (o < DO_) {
        float s0 = 0.f, s1 = 0.f, s2 = 0.f, s3 = 0.f;
        const float* ag = agg[r4];
        #pragma unroll
        for (int c0 = 0; c0 < DC; c0 += 4) {
            s0 = fmaf(ag[c0    ], W_n[(DN + c0    )*DO_ + o], s0);
            s1 = fmaf(ag[c0 + 1], W_n[(DN + c0 + 1)*DO_ + o], s1);
            s2 = fmaf(ag[c0 + 2], W_n[(DN + c0 + 2)*DO_ + o], s2);
            s3 = fmaf(ag[c0 + 3], W_n[(DN + c0 + 3)*DO_ + o], s3);
        }
        out[(size_t)bn*DO_ + o] += (s0 + s1) + (s2 + s3);
    }
}

// ---------------------------------------------------------------------------
extern "C" void kernel_launch(void* const* d_in, const int* in_sizes, int n_in,
                              void* d_out, int out_size) {
    const float* node = (const float*)d_in[0];
    const float* edge = (const float*)d_in[1];
    const float* adjp = (const float*)d_in[2];
    const float* W_e  = (const float*)d_in[3];
    const float* b_e  = (const float*)d_in[4];
    const float* W_n  = (const float*)d_in[5];
    const float* b_n  = (const float*)d_in[6];
    float* out = (float*)d_out;

    cudaFuncSetAttribute(edge_kernel, cudaFuncAttributeMaxDynamicSharedMemorySize, SMEM_DYN);

    precompute_kernel<<<B_*N_/PCN, 256>>>(node, W_e, b_e, W_n, b_n, out);
    edge_kernel<<<GRID, 256, SMEM_DYN>>>(edge, adjp, W_e);
    fold_kernel<<<B_*N_/4, 256>>>(W_n, out);
}

// round 17
// speedup vs baseline: 1.1080x; 1.1080x over previous
#include <cuda_runtime.h>
#include <cstdint>

#define B_  8
#define N_  256
#define DN  64
#define DE  32
#define DC  64
#define DO_ 60
#define CPB  37           // CTAs per batch
#define GRID (8*CPB)      // 296

__device__ __align__(16) float g_pr  [B_*N_*DC];
__device__ __align__(16) float g_psb [B_*N_*DC];
__device__ __align__(16) float g_part[B_*N_*8*DC];   // per-warp partial aggs (4 MB)

// ---------------------------------------------------------------------------
// Kernel A: per-node precompute. 8 nodes/block, 2 nodes/thread. ALL weights
// staged in smem once per block -> inner loop is pure LDS + FMA (no L2
// latency in the chain).
//   smem: Wes[8192] = W_e rows 32..159 | Wns[3904] = W_n rows 0..63 (padded)
//         | nrowS[512]
// ---------------------------------------------------------------------------
#define PCN 8
#define PC_WES 8192
#define PC_WNS 3904          // 3840 used + pad (k*60+c max 3843)
#define PC_NRW 512
#define PC_SMEM ((PC_WES + PC_WNS + PC_NRW) * 4)   // 50432 B

__global__ void __launch_bounds__(256) precompute_kernel(
    const float* __restrict__ node,
    const float* __restrict__ W_e,
    const float* __restrict__ b_e,
    const float* __restrict__ W_n,
    const float* __restrict__ b_n,
    float* __restrict__ out) {

    extern __shared__ __align__(16) float psm[];
    float* Wes   = psm;                    // [k 0..127][c 0..63]
    float* Wns   = psm + PC_WES;           // [k 0..63][o 0..59]
    float* nrowS = psm + PC_WES + PC_WNS;  // [n 0..7][k 0..63]

    const int tid = threadIdx.x;
    const int c   = tid & 63;
    const int ng  = tid >> 6;              // 0..3
    const int bn0 = blockIdx.x * PCN;

    // --- stage weights + node rows (coalesced float4) ---
    {
        const float4* ws = (const float4*)(W_e + DE*DC);     // 2048 float4
        float4* wd = (float4*)Wes;
        #pragma unroll
        for (int i = 0; i < 8; i++) wd[tid + i*256] = ws[tid + i*256];

        const float4* wn4 = (const float4*)W_n;              // 960 float4
        float4* wnd = (float4*)Wns;
        #pragma unroll
        for (int i = 0; i < 4; i++) {
            int idx = tid + i*256;
            if (idx < 960) wnd[idx] = wn4[idx];
        }
        const float4* ns = (const float4*)(node + (size_t)bn0*DN);  // 128 float4
        if (tid < 128) ((float4*)nrowS)[tid] = ns[tid];
    }
    __syncthreads();

    const int n0 = 2*ng, n1 = 2*ng + 1;
    float aR0 = 0.f, aR1 = 0.f, aS0 = 0.f, aS1 = 0.f, aO0 = 0.f, aO1 = 0.f;

    #pragma unroll 16
    for (int k = 0; k < DN; k++) {
        const float wR  = Wes[k*DC + c];
        const float wS  = Wes[(DN + k)*DC + c];
        const float wO  = Wns[k*DO_ + c];          // padded; unused for c>=60
        const float nv0 = nrowS[n0*DN + k];
        const float nv1 = nrowS[n1*DN + k];
        aR0 = fmaf(nv0, wR, aR0);  aR1 = fmaf(nv1, wR, aR1);
        aS0 = fmaf(nv0, wS, aS0);  aS1 = fmaf(nv1, wS, aS1);
        aO0 = fmaf(nv0, wO, aO0);  aO1 = fmaf(nv1, wO, aO1);
    }

    g_pr [(bn0 + n0)*DC + c] = aR0;
    g_pr [(bn0 + n1)*DC + c] = aR1;
    const float be = b_e[c];
    g_psb[(bn0 + n0)*DC + c] = aS0 + be;
    g_psb[(bn0 + n1)*DC + c] = aS1 + be;
    if (c < DO_) {
        const float bo = b_n[c];
        out[(size_t)(bn0 + n0)*DO_ + c] = aO0 + bo;
        out[(size_t)(bn0 + n1)*DO_ + c] = aO1 + bo;
    }
}

// ---------------------------------------------------------------------------
// tf32 / math / async helpers
// ---------------------------------------------------------------------------
__device__ __forceinline__ uint32_t tf32r(float f) {
    uint32_t u;
    asm("cvt.rna.tf32.f32 %0, %1;" : "=r"(u) : "f"(f));
    return u;
}
__device__ __forceinline__ void mma_1688(float c[4],
                                         const uint32_t a[4],
                                         uint32_t b0, uint32_t b1) {
    asm volatile("mma.sync.aligned.m16n8k8.row.col.f32.tf32.tf32.f32 "
                 "{%0,%1,%2,%3}, {%4,%5,%6,%7}, {%8,%9}, {%0,%1,%2,%3};"
                 : "+f"(c[0]), "+f"(c[1]), "+f"(c[2]), "+f"(c[3])
                 : "r"(a[0]), "r"(a[1]), "r"(a[2]), "r"(a[3]), "r"(b0), "r"(b1));
}
__device__ __forceinline__ void cp16(uint32_t smem_addr, const void* gptr) {
    asm volatile("cp.async.cg.shared.global [%0], [%1], 16;"
                 :: "r"(smem_addr), "l"(gptr));
}
// leaky-relu then scaled accumulate: u += a * max(x, 0.01x)
__device__ __forceinline__ float lracc(float u, float a, float x) {
    return fmaf(a, fmaxf(x, 0.01f * x), u);
}

#define ESTRIDE 36    // bank = 4g + t  -> conflict-free A-frag loads
#define PSTRIDE 268   // float2 stride; conflict-free per 16-lane phase

// Dynamic smem layout (bytes)
#define OFF_E0   0u          // half-tile buf0: 128*36*4 = 18432
#define OFF_E1   18432u      // half-tile buf1: 18432
#define OFF_PSB  36864u      // psb2 float2[32][268] = 68608
#define OFF_PRS  105472u     // pr staged: 7*64 f32 = 1792
#define SMEM_DYN 107264u     // -> 2 CTAs/SM

// ---------------------------------------------------------------------------
// Kernel B: batch-locked persistent CTAs; psb packed float2 in smem; B-frags
// register-resident; warp-private cp.async E pipeline. NO CTA barrier in the
// receiver loop: per-warp partials go to gmem; fold kernel combines.
// ---------------------------------------------------------------------------
__global__ void __launch_bounds__(256, 2) edge_kernel(
    const float* __restrict__ edge_attr,
    const float* __restrict__ adj,
    const float* __restrict__ W_e) {

    extern __shared__ __align__(16) unsigned char dynsm[];
    float2* psb2 = (float2*)(dynsm + OFF_PSB);
    float*  prS  = (float*) (dynsm + OFF_PRS);
    const uint32_t esm0 = (uint32_t)__cvta_generic_to_shared(dynsm);

    const int tid  = threadIdx.x;
    const int bx   = blockIdx.x;
    const int wid  = tid >> 5;             // 0..7
    const int lane = tid & 31;
    const int g    = lane >> 2;            // 0..7
    const int t    = lane & 3;             // 0..3

    const int batch = bx / CPB;
    const int cb    = bx % CPB;
    const int rs    = (cb * N_) / CPB;
    const int re    = ((cb + 1) * N_) / CPB;
    const int nr    = re - rs;             // 6 or 7
    const int bn0   = batch * N_ + rs;

    // warp-private E row mapping: lane l loads rows 16w + (l>>3) + 4i, chunk l&7
    const int erow = 16*wid + (lane >> 3);
    const int eq   = lane & 7;

    // --- fire first half-load (receiver bn0, half 0) into buf0 ---
    {
        const float* esrc = edge_attr + (size_t)bn0 * (N_*DE);
        #pragma unroll
        for (int i = 0; i < 4; i++) {
            int r = erow + 4*i;
            cp16(esm0 + (uint32_t)(r*ESTRIDE + eq*4)*4u, esrc + r*DE + eq*4);
        }
        asm volatile("cp.async.commit_group;");
    }

    // --- B-fragments register-resident (one-time gmem loads, L2-shared) ---
    uint32_t bfr[8][4][2];
    #pragma unroll
    for (int nt = 0; nt < 8; nt++)
        #pragma unroll
        for (int ks = 0; ks < 4; ks++) {
            bfr[nt][ks][0] = tf32r(__ldg(W_e + (8*ks + t    )*DC + 8*nt + g));
            bfr[nt][ks][1] = tf32r(__ldg(W_e + (8*ks + t + 4)*DC + 8*nt + g));
        }

    // --- stage psb2 for this batch (once): cp = lane, s = 8i + wid ---
    {
        const float2* psrc = (const float2*)g_psb + (size_t)batch * (N_*DC/2);
        #pragma unroll
        for (int i = 0; i < 32; i++) {
            const int s  = 8*i + wid;      // 0..255
            const int cp = lane;           // 0..31
            psb2[cp*PSTRIDE + s] = psrc[s*32 + cp];
        }
    }
    // --- stage pr for all this CTA's receivers (once) ---
    for (int idx = tid; idx < nr*DC; idx += 256)
        prS[idx] = g_pr[(size_t)bn0*DC + idx];
    __syncthreads();                        // the ONLY CTA barrier

    for (int ri = 0; ri < nr; ri++) {
        const int bn = bn0 + ri;
        const float* prp = prS + ri*DC + 2*t;   // smem

        float ux[8], uy[8];
        #pragma unroll
        for (int nt = 0; nt < 8; nt++) { ux[nt] = 0.f; uy[nt] = 0.f; }

        #pragma unroll
        for (int h = 0; h < 2; h++) {
            const int m = 2*ri + h;

            // --- prefetch next half (warp-private rows) ---
            if (m + 1 < 2*nr) {
                const int rn = (m + 1) >> 1, hn = (m + 1) & 1;
                const float* esrc = edge_attr
                    + (size_t)(bn0 + rn) * (N_*DE) + hn * (128*DE);
                const uint32_t eb = esm0 + (uint32_t)((m + 1) & 1) * OFF_E1;
                #pragma unroll
                for (int i = 0; i < 4; i++) {
                    int r = erow + 4*i;
                    cp16(eb + (uint32_t)(r*ESTRIDE + eq*4)*4u, esrc + r*DE + eq*4);
                }
                asm volatile("cp.async.commit_group;");
                asm volatile("cp.async.wait_group 1;" ::: "memory");
            } else {
                asm volatile("cp.async.wait_group 0;" ::: "memory");
            }
            __syncwarp();                   // intra-warp visibility only

            const int sg_lo = h*128 + 16*wid + g;    // global sender of row lo
            const float a_lo = __ldg(adj + (size_t)bn*N_ + sg_lo);
            const float a_hi = __ldg(adj + (size_t)bn*N_ + sg_lo + 8);

            // --- A fragments from current half buffer (own rows only) ---
            const uint32_t* Eb = (const uint32_t*)(dynsm + (m & 1)*OFF_E1);
            const int lo = 16*wid + g, hi = lo + 8;
            uint32_t afr[4][4];
            #pragma unroll
            for (int ks = 0; ks < 4; ks++) {
                const int k0 = 8*ks + t;
                afr[ks][0] = tf32r(__uint_as_float(Eb[lo*ESTRIDE + k0    ]));
                afr[ks][1] = tf32r(__uint_as_float(Eb[hi*ESTRIDE + k0    ]));
                afr[ks][2] = tf32r(__uint_as_float(Eb[lo*ESTRIDE + k0 + 4]));
                afr[ks][3] = tf32r(__uint_as_float(Eb[hi*ESTRIDE + k0 + 4]));
            }

            #pragma unroll
            for (int nt = 0; nt < 8; nt += 2) {
                const int cpA = 4*nt + t;          // channel pair 8nt+2t
                const int cpB = cpA + 4;           // channel pair 8(nt+1)+2t
                const float2 prA = *(const float2*)(prp + 8*nt);
                const float2 prB = *(const float2*)(prp + 8*nt + 8);

                const float2 pAlo = psb2[cpA*PSTRIDE + sg_lo];
                const float2 pAhi = psb2[cpA*PSTRIDE + sg_lo + 8];
                const float2 pBlo = psb2[cpB*PSTRIDE + sg_lo];
                const float2 pBhi = psb2[cpB*PSTRIDE + sg_lo + 8];

                float acc0[4] = { pAlo.x + prA.x, pAlo.y + prA.y,
                                  pAhi.x + prA.x, pAhi.y + prA.y };
                float acc1[4] = { pBlo.x + prB.x, pBlo.y + prB.y,
                                  pBhi.x + prB.x, pBhi.y + prB.y };

                #pragma unroll
                for (int ks = 0; ks < 4; ks++) {
                    mma_1688(acc0, afr[ks], bfr[nt    ][ks][0], bfr[nt    ][ks][1]);
                    mma_1688(acc1, afr[ks], bfr[nt + 1][ks][0], bfr[nt + 1][ks][1]);
                }

                ux[nt]   = lracc(lracc(ux[nt],   a_lo, acc0[0]), a_hi, acc0[2]);
                uy[nt]   = lracc(lracc(uy[nt],   a_lo, acc0[1]), a_hi, acc0[3]);
                ux[nt+1] = lracc(lracc(ux[nt+1], a_lo, acc1[0]), a_hi, acc1[2]);
                uy[nt+1] = lracc(lracc(uy[nt+1], a_lo, acc1[1]), a_hi, acc1[3]);
            }
        } // halves

        // --- cross-lane butterfly over the 8 groups; lanes 0-3 own channels ---
        #pragma unroll
        for (int nt = 0; nt < 8; nt++) {
            #pragma unroll
            for (int st = 4; st <= 16; st <<= 1) {
                ux[nt] += __shfl_xor_sync(0xffffffffu, ux[nt], st);
                uy[nt] += __shfl_xor_sync(0xffffffffu, uy[nt], st);
            }
        }
        // --- warp-private partials straight to gmem: no CTA sync needed ---
        if (lane < 4) {
            float* pp = g_part + ((size_t)bn*8 + wid)*DC;
            #pragma unroll
            for (int nt = 0; nt < 8; nt++)
                *(float2*)(pp + 8*nt + 2*t) = make_float2(ux[nt], uy[nt]);
        }
    } // receivers
}

// ---------------------------------------------------------------------------
// Kernel C: fold. agg[c] = sum_w part[bn][w][c]; out[bn] += agg @ W_n[64:128].
// ---------------------------------------------------------------------------
__global__ void __launch_bounds__(256) fold_kernel(const float* __restrict__ W_n,
                                                   float* __restrict__ out) {
    __shared__ float agg[4][DC];
    const int tid = threadIdx.x;
    const int r4  = tid >> 6;               // 0..3
    const int o   = tid & 63;               // 0..63
    const int bn  = blockIdx.x*4 + r4;

    const float* pp = g_part + (size_t)bn*8*DC + o;
    float a = 0.f;
    #pragma unroll
    for (int w = 0; w < 8; w++) a += pp[w*DC];
    agg[r4][o] = a;
    __syncthreads();

    if (o < DO_) {
        float s0 = 0.f, s1 = 0.f, s2 = 0.f, s3 = 0.f;
        const float* ag = agg[r4];
        #pragma unroll
        for (int c0 = 0; c0 < DC; c0 += 4) {
            s0 = fmaf(ag[c0    ], W_n[(DN + c0    )*DO_ + o], s0);
            s1 = fmaf(ag[c0 + 1], W_n[(DN + c0 + 1)*DO_ + o], s1);
            s2 = fmaf(ag[c0 + 2], W_n[(DN + c0 + 2)*DO_ + o], s2);
            s3 = fmaf(ag[c0 + 3], W_n[(DN + c0 + 3)*DO_ + o], s3);
        }
        out[(size_t)bn*DO_ + o] += (s0 + s1) + (s2 + s3);
    }
}

// ---------------------------------------------------------------------------
extern "C" void kernel_launch(void* const* d_in, const int* in_sizes, int n_in,
                              void* d_out, int out_size) {
    const float* node = (const float*)d_in[0];
    const float* edge = (const float*)d_in[1];
    const float* adjp = (const float*)d_in[2];
    const float* W_e  = (const float*)d_in[3];
    const float* b_e  = (const float*)d_in[4];
    const float* W_n  = (const float*)d_in[5];
    const float* b_n  = (const float*)d_in[6];
    float* out = (float*)d_out;

    cudaFuncSetAttribute(edge_kernel, cudaFuncAttributeMaxDynamicSharedMemorySize, SMEM_DYN);
    cudaFuncSetAttribute(precompute_kernel, cudaFuncAttributeMaxDynamicSharedMemorySize, PC_SMEM);

    precompute_kernel<<<B_*N_/PCN, 256, PC_SMEM>>>(node, W_e, b_e, W_n, b_n, out);
    edge_kernel<<<GRID, 256, SMEM_DYN>>>(edge, adjp, W_e);
    fold_kernel<<<B_*N_/4, 256>>>(W_n, out);
}